// round 14
// baseline (speedup 1.0000x reference)
#include <cuda_runtime.h>
#include <cstdint>

// MultiNetwork: 32 MLPs 256->512->512->128 (relu, relu, id), batch 4096.
// Round 14: round-13 mbarrier pipeline, but 4 warps of 64x64 (128 threads,
// warp grid 2x2). Cuts ldsm crossbar traffic 96->64 KB/chunk so the tensor
// pipe (1024 cyc/chunk) finally exceeds smem demand (~790 cyc). 2 CTAs/SM.

#define DINLINE __device__ __forceinline__

static constexpr int NETS  = 32;
static constexpr int BATCH = 4096;
static constexpr int D_IN  = 256;
static constexpr int D_H   = 512;
static constexpr int D_OUT = 128;

static constexpr int NT = 128;    // threads per CTA
static constexpr int MT = 128;    // CTA batch tile
static constexpr int NC = 128;    // CTA output tile (per segment)
static constexpr int KC = 32;     // K chunk
static constexpr int LD = 36;     // padded smem row stride (floats)

static constexpr int A_F = MT * LD;               // 4608 floats
static constexpr int B_F = NC * LD;               // 4608 floats
static constexpr int A_BYTES     = A_F * 4;       // 18432
static constexpr int STAGE_BYTES = (A_F + B_F) * 4;   // 36864
static constexpr int SM_STAGE0   = 64;            // barriers live in [0,48)
static constexpr int SMEM_BYTES  = SM_STAGE0 + 3 * STAGE_BYTES;  // 110656

// Pre-rounded (tf32/rna) operands + inter-layer activations.
__device__ float g_xr [(size_t)BATCH * D_IN];
__device__ float g_w1r[(size_t)NETS * D_H   * D_IN];
__device__ float g_w2r[(size_t)NETS * D_H   * D_H];
__device__ float g_w3r[(size_t)NETS * D_OUT * D_H];
__device__ float g_h1 [(size_t)NETS * BATCH * D_H];
__device__ float g_h2 [(size_t)NETS * BATCH * D_H];

DINLINE uint32_t smem_u32(const void* p) {
    uint32_t a;
    asm("{ .reg .u64 t; cvta.to.shared.u64 t, %1; cvt.u32.u64 %0, t; }" : "=r"(a) : "l"(p));
    return a;
}
DINLINE uint32_t tf32r(float x) {
    uint32_t u;
    asm("cvt.rna.tf32.f32 %0, %1;" : "=r"(u) : "f"(x));
    return u;
}
DINLINE void cpasync16(uint32_t dst, const void* src) {
    asm volatile("cp.async.cg.shared.global [%0], [%1], 16;"
                 :: "r"(dst), "l"(src) : "memory");
}
DINLINE void mbar_init(uint32_t a, uint32_t cnt) {
    asm volatile("mbarrier.init.shared.b64 [%0], %1;" :: "r"(a), "r"(cnt) : "memory");
}
DINLINE void mbar_arrive(uint32_t a) {
    asm volatile("mbarrier.arrive.shared.b64 _, [%0];" :: "r"(a) : "memory");
}
// Arrive on mbar once all of this thread's prior cp.asyncs have completed.
DINLINE void cp_mbar_arrive(uint32_t a) {
    asm volatile("cp.async.mbarrier.arrive.noinc.shared.b64 [%0];" :: "r"(a) : "memory");
}
DINLINE void mbar_wait(uint32_t a, uint32_t parity) {
    asm volatile(
        "{\n\t"
        ".reg .pred P;\n\t"
        "WL%=:\n\t"
        "mbarrier.try_wait.parity.acquire.cta.shared::cta.b64 P, [%0], %1, 0x989680;\n\t"
        "@P bra.uni WD%=;\n\t"
        "bra.uni WL%=;\n\t"
        "WD%=:\n\t"
        "}" :: "r"(a), "r"(parity) : "memory");
}
DINLINE void ldsm4(uint32_t* r, uint32_t addr) {
    asm volatile("ldmatrix.sync.aligned.m8n8.x4.shared.b16 {%0,%1,%2,%3}, [%4];"
                 : "=r"(r[0]), "=r"(r[1]), "=r"(r[2]), "=r"(r[3]) : "r"(addr));
}
DINLINE void mma8(float* d, const uint32_t* a, const uint32_t* b) {
    asm volatile(
        "mma.sync.aligned.m16n8k8.row.col.f32.tf32.tf32.f32 "
        "{%0,%1,%2,%3}, {%4,%5,%6,%7}, {%8,%9}, {%0,%1,%2,%3};"
        : "+f"(d[0]), "+f"(d[1]), "+f"(d[2]), "+f"(d[3])
        : "r"(a[0]), "r"(a[1]), "r"(a[2]), "r"(a[3]), "r"(b[0]), "r"(b[1]));
}

// barrier addresses: FULL(s) = sb + s*16, EMPTY(s) = sb + s*16 + 8
#define FULLB(s)  (sb + (uint32_t)(s) * 16)
#define EMPTYB(s) (sb + (uint32_t)(s) * 16 + 8)

// One layer = NSEG segments of C[128, NC] = A[128,K] * Bseg^T (+bias, relu?).
// Continuous chunk pipeline across segments; mbarrier-decoupled stages.
// 4 warps, grid 2(M) x 2(N); warp tile 64x64 (MF=4, NF=8).
template<int NSEG, int NK, bool ISOUT>
DINLINE void run_layer(int& cc, uint32_t sb,
                       const float* __restrict__ Asrc, int As,
                       const float* __restrict__ Wbase,
                       const float* __restrict__ biasBase,
                       float* __restrict__ dstBase, int dstride)
{
    extern __shared__ float smf[];
    const int tid  = threadIdx.x;
    const int lane = tid & 31, wid = tid >> 5;
    const int gid  = lane >> 2, tig = lane & 3;
    const int wm   = wid & 1, wn = wid >> 1;        // 2 x 2 warps, tile 64x64
    constexpr int K   = NK * KC;
    constexpr int TOT = NSEG * NK;

    float acc[4][8][4];
    #pragma unroll
    for (int i = 0; i < 4; i++)
        #pragma unroll
        for (int j = 0; j < 8; j++)
            #pragma unroll
            for (int q = 0; q < 4; q++) acc[i][j][q] = 0.0f;

    auto fill = [&](int lc) {
        const int c   = cc + lc;
        const int stg = c % 3;
        const int seg = lc / NK, kk = lc % NK;
        if (c >= 3) mbar_wait(EMPTYB(stg), (uint32_t)(((c / 3) - 1) & 1));
        const uint32_t base = sb + SM_STAGE0 + stg * STAGE_BYTES;
        const float* Ap = Asrc + kk * KC;
        const float* Bp = Wbase + (size_t)seg * ((size_t)NC * K) + kk * KC;
        #pragma unroll
        for (int i = 0; i < 8; i++) {                 // A: 8 quads/thread
            int f = tid + i * NT, r = f >> 3, cq = f & 7;
            cpasync16(base + (uint32_t)(r * LD + cq * 4) * 4,
                      Ap + (size_t)r * As + cq * 4);
        }
        #pragma unroll
        for (int i = 0; i < 8; i++) {                 // B: 8 quads/thread
            int f = tid + i * NT, r = f >> 3, cq = f & 7;
            cpasync16(base + A_BYTES + (uint32_t)(r * LD + cq * 4) * 4,
                      Bp + (size_t)r * K + cq * 4);
        }
        cp_mbar_arrive(FULLB(stg));
    };

    // per-lane ldmatrix byte offsets
    const uint32_t aoff = (uint32_t)(((lane & 15) * LD + ((lane >> 4) & 1) * 4) * 4);
    const uint32_t boff = (uint32_t)(((((lane >> 4) & 1) * 8 + (lane & 7)) * LD
                                      + ((lane >> 3) & 1) * 4) * 4);

    auto compute = [&](int stg) {
        const uint32_t Ab = sb + SM_STAGE0 + stg * STAGE_BYTES
                          + (uint32_t)(wm * 64 * LD * 4) + aoff;
        const uint32_t Bb = sb + SM_STAGE0 + stg * STAGE_BYTES + A_BYTES
                          + (uint32_t)(wn * 64 * LD * 4) + boff;
        #pragma unroll
        for (int ks = 0; ks < 4; ks++) {
            const uint32_t k0b = (uint32_t)(ks * 32);
            uint32_t a[4][4];
            #pragma unroll
            for (int mf = 0; mf < 4; mf++)
                ldsm4(a[mf], Ab + (uint32_t)(mf * 16 * LD * 4) + k0b);
            #pragma unroll
            for (int p = 0; p < 4; p++) {
                uint32_t bt[4];
                ldsm4(bt, Bb + (uint32_t)(p * 16 * LD * 4) + k0b);
                #pragma unroll
                for (int mf = 0; mf < 4; mf++) {
                    mma8(acc[mf][2 * p],     a[mf], bt);
                    mma8(acc[mf][2 * p + 1], a[mf], bt + 2);
                }
            }
        }
    };

    fill(0); fill(1);

    #pragma unroll 1
    for (int lc = 0; lc < TOT; lc++) {
        if (lc + 2 < TOT) fill(lc + 2);
        const int c = cc + lc, stg = c % 3;
        mbar_wait(FULLB(stg), (uint32_t)((c / 3) & 1));
        compute(stg);
        mbar_arrive(EMPTYB(stg));   // after compute: all ldsm reads consumed

        if ((lc & (NK - 1)) == NK - 1) {
            // segment epilogue (overlaps other warps' compute — no barrier)
            const int seg = lc / NK;
            #pragma unroll
            for (int mf = 0; mf < 4; mf++) {
                #pragma unroll
                for (int nf = 0; nf < 8; nf++) {
                    const int rr  = wm * 64 + mf * 16 + gid;
                    const int col = seg * NC + wn * 64 + nf * 8 + tig * 2;
                    const float b0 = __ldg(biasBase + col);
                    const float b1 = __ldg(biasBase + col + 1);
                    float v00 = acc[mf][nf][0] + b0, v01 = acc[mf][nf][1] + b1;
                    float v10 = acc[mf][nf][2] + b0, v11 = acc[mf][nf][3] + b1;
                    if (!ISOUT) {
                        v00 = fmaxf(v00, 0.0f); v01 = fmaxf(v01, 0.0f);
                        v10 = fmaxf(v10, 0.0f); v11 = fmaxf(v11, 0.0f);
                        float2 lo = make_float2(__uint_as_float(tf32r(v00)),
                                                __uint_as_float(tf32r(v01)));
                        float2 hi = make_float2(__uint_as_float(tf32r(v10)),
                                                __uint_as_float(tf32r(v11)));
                        *reinterpret_cast<float2*>(
                            dstBase + (size_t)rr * dstride + col) = lo;
                        *reinterpret_cast<float2*>(
                            dstBase + (size_t)(rr + 8) * dstride + col) = hi;
                    } else {
                        *reinterpret_cast<float2*>(
                            dstBase + (size_t)rr * dstride + col) =
                            make_float2(v00, v01);
                        *reinterpret_cast<float2*>(
                            dstBase + (size_t)(rr + 8) * dstride + col) =
                            make_float2(v10, v11);
                    }
                    acc[mf][nf][0] = 0.0f; acc[mf][nf][1] = 0.0f;
                    acc[mf][nf][2] = 0.0f; acc[mf][nf][3] = 0.0f;
                }
            }
        }
    }
    cc += TOT;

    if (!ISOUT) {   // h must be globally visible to next layer's cp.async
        asm volatile("membar.gl;" ::: "memory");
        __syncthreads();
    }
}

__global__ void __launch_bounds__(NT, 2)
multinet14(const float* __restrict__ b1, const float* __restrict__ b2,
           const float* __restrict__ b3, float* __restrict__ out)
{
    extern __shared__ float smf[];
    const uint32_t sb = smem_u32(smf);
    const int m0 = blockIdx.x * MT;
    const int g  = blockIdx.y;

    if (threadIdx.x == 0) {
        #pragma unroll
        for (int s = 0; s < 3; s++) {
            mbar_init(FULLB(s), NT);     // 1 cp-arrive per thread per fill
            mbar_init(EMPTYB(s), NT);    // 1 arrive per thread per compute
        }
    }
    __syncthreads();

    float* h1 = g_h1 + ((size_t)g * BATCH + m0) * D_H;
    float* h2 = g_h2 + ((size_t)g * BATCH + m0) * D_H;

    int cc = 0;
    // layer 1: 4 segs x 8 chunks (K=256)
    run_layer<4, 8, false>(cc, sb, g_xr + (size_t)m0 * D_IN, D_IN,
                           g_w1r + (size_t)g * D_H * D_IN,
                           b1 + (size_t)g * D_H, h1, D_H);
    // layer 2: 4 segs x 16 chunks (K=512)
    run_layer<4, 16, false>(cc, sb, h1, D_H,
                            g_w2r + (size_t)g * D_H * D_H,
                            b2 + (size_t)g * D_H, h2, D_H);
    // layer 3: 1 seg x 16 chunks (identity)
    run_layer<1, 16, true>(cc, sb, h2, D_H,
                           g_w3r + (size_t)g * D_OUT * D_H,
                           b3 + (size_t)g * D_OUT,
                           out + (size_t)m0 * (NETS * D_OUT) + g * D_OUT,
                           NETS * D_OUT);
}

// Fused fp32 -> tf32(rna) pre-round of x, W1, W2, W3 (one launch).
__global__ void round_all(const float* __restrict__ x,
                          const float* __restrict__ W1,
                          const float* __restrict__ W2,
                          const float* __restrict__ W3)
{
    constexpr size_t N0 = (size_t)BATCH * D_IN / 4;
    constexpr size_t N1 = (size_t)NETS * D_H * D_IN / 4;
    constexpr size_t N2 = (size_t)NETS * D_H * D_H / 4;
    constexpr size_t N3 = (size_t)NETS * D_OUT * D_H / 4;

    size_t j = (size_t)blockIdx.x * blockDim.x + threadIdx.x;
    const float4* src; float4* dst;
    if (j < N0)              { src = (const float4*)x;  dst = (float4*)g_xr; }
    else if ((j -= N0) < N1) { src = (const float4*)W1; dst = (float4*)g_w1r; }
    else if ((j -= N1) < N2) { src = (const float4*)W2; dst = (float4*)g_w2r; }
    else if ((j -= N2) < N3) { src = (const float4*)W3; dst = (float4*)g_w3r; }
    else return;

    float4 v = src[j];
    dst[j] = make_float4(__uint_as_float(tf32r(v.x)), __uint_as_float(tf32r(v.y)),
                         __uint_as_float(tf32r(v.z)), __uint_as_float(tf32r(v.w)));
}

extern "C" void kernel_launch(void* const* d_in, const int* in_sizes, int n_in,
                              void* d_out, int out_size)
{
    const float* x  = (const float*)d_in[0];
    const float* W1 = (const float*)d_in[1];
    const float* b1 = (const float*)d_in[2];
    const float* W2 = (const float*)d_in[3];
    const float* b2 = (const float*)d_in[4];
    const float* W3 = (const float*)d_in[5];
    const float* b3 = (const float*)d_in[6];
    float* out = (float*)d_out;

    constexpr size_t TOTQ = ((size_t)BATCH * D_IN + (size_t)NETS * D_H * D_IN
                           + (size_t)NETS * D_H * D_H + (size_t)NETS * D_OUT * D_H) / 4;
    round_all<<<(unsigned)((TOTQ + 255) / 256), 256>>>(x, W1, W2, W3);

    cudaFuncSetAttribute(multinet14,
                         cudaFuncAttributeMaxDynamicSharedMemorySize, SMEM_BYTES);
    dim3 grid(BATCH / MT, NETS);   // 32 x 32 = 1024 CTAs
    multinet14<<<grid, NT, SMEM_BYTES>>>(b1, b2, b3, out);
}

// round 16
// speedup vs baseline: 1.7084x; 1.7084x over previous
#include <cuda_runtime.h>
#include <cuda_fp16.h>
#include <cstdint>

// MultiNetwork: 32 MLPs 256->512->512->128 (relu, relu, id), batch 4096.
// Round 16 (= round 15 re-bench; previous run died on container infra).
// fp16 operands (same 11-bit significand as tf32 -> same accuracy), fp32
// accumulate via mma.m16n8k16 (2x MACs/instruction -> halves the mma issue
// floor). KC=64 in the same 36.9KB stage halves chunk count and per-chunk
// overheads. 3-stage mbarrier pipeline, 4 warps of 64x64, 2 CTAs/SM.

#define DINLINE __device__ __forceinline__

static constexpr int NETS  = 32;
static constexpr int BATCH = 4096;
static constexpr int D_IN  = 256;
static constexpr int D_H   = 512;
static constexpr int D_OUT = 128;

static constexpr int NT = 128;    // threads per CTA (4 warps, grid 2x2, tile 64x64)
static constexpr int MT = 128;    // CTA batch tile
static constexpr int NC = 128;    // CTA output tile (per segment)
static constexpr int KC = 64;     // K chunk (halfs) -> 128B per row
static constexpr int LD = 72;     // padded smem row stride (halfs, 144B)

static constexpr int A_BYTES     = MT * LD * 2;            // 18432
static constexpr int STAGE_BYTES = (MT + NC) * LD * 2;     // 36864
static constexpr int SM_STAGE0   = 64;                     // barriers in [0,48)
static constexpr int SMEM_BYTES  = SM_STAGE0 + 3 * STAGE_BYTES;  // 110656

// fp16 operands + inter-layer activations (fp16), biases stay fp32.
__device__ __half g_xh [(size_t)BATCH * D_IN];
__device__ __half g_w1h[(size_t)NETS * D_H   * D_IN];
__device__ __half g_w2h[(size_t)NETS * D_H   * D_H];
__device__ __half g_w3h[(size_t)NETS * D_OUT * D_H];
__device__ __half g_h1 [(size_t)NETS * BATCH * D_H];
__device__ __half g_h2 [(size_t)NETS * BATCH * D_H];

DINLINE uint32_t smem_u32(const void* p) {
    uint32_t a;
    asm("{ .reg .u64 t; cvta.to.shared.u64 t, %1; cvt.u32.u64 %0, t; }" : "=r"(a) : "l"(p));
    return a;
}
DINLINE void cpasync16(uint32_t dst, const void* src) {
    asm volatile("cp.async.cg.shared.global [%0], [%1], 16;"
                 :: "r"(dst), "l"(src) : "memory");
}
DINLINE void mbar_init(uint32_t a, uint32_t cnt) {
    asm volatile("mbarrier.init.shared.b64 [%0], %1;" :: "r"(a), "r"(cnt) : "memory");
}
DINLINE void mbar_arrive(uint32_t a) {
    asm volatile("mbarrier.arrive.shared.b64 _, [%0];" :: "r"(a) : "memory");
}
DINLINE void cp_mbar_arrive(uint32_t a) {
    asm volatile("cp.async.mbarrier.arrive.noinc.shared.b64 [%0];" :: "r"(a) : "memory");
}
DINLINE void mbar_wait(uint32_t a, uint32_t parity) {
    asm volatile(
        "{\n\t"
        ".reg .pred P;\n\t"
        "WL%=:\n\t"
        "mbarrier.try_wait.parity.acquire.cta.shared::cta.b64 P, [%0], %1, 0x989680;\n\t"
        "@P bra.uni WD%=;\n\t"
        "bra.uni WL%=;\n\t"
        "WD%=:\n\t"
        "}" :: "r"(a), "r"(parity) : "memory");
}
DINLINE void ldsm4(uint32_t* r, uint32_t addr) {
    asm volatile("ldmatrix.sync.aligned.m8n8.x4.shared.b16 {%0,%1,%2,%3}, [%4];"
                 : "=r"(r[0]), "=r"(r[1]), "=r"(r[2]), "=r"(r[3]) : "r"(addr));
}
// fp16 mma, fp32 accumulate, 16x8x16.
DINLINE void mma16(float* d, const uint32_t* a, const uint32_t* b) {
    asm volatile(
        "mma.sync.aligned.m16n8k16.row.col.f32.f16.f16.f32 "
        "{%0,%1,%2,%3}, {%4,%5,%6,%7}, {%8,%9}, {%0,%1,%2,%3};"
        : "+f"(d[0]), "+f"(d[1]), "+f"(d[2]), "+f"(d[3])
        : "r"(a[0]), "r"(a[1]), "r"(a[2]), "r"(a[3]), "r"(b[0]), "r"(b[1]));
}

#define FULLB(s)  (sb + (uint32_t)(s) * 16)
#define EMPTYB(s) (sb + (uint32_t)(s) * 16 + 8)

// One layer = NSEG segments of C[128, NC] = A[128,K] * Bseg^T (+bias, relu?).
// K streamed in KC=64 chunks; mbarrier-decoupled 3-stage pipeline.
template<int NSEG, int NK, bool ISOUT, typename DT>
DINLINE void run_layer(int& cc, uint32_t sb,
                       const __half* __restrict__ Asrc, int As,
                       const __half* __restrict__ Wbase,
                       const float* __restrict__ biasBase,
                       DT* __restrict__ dstBase, int dstride)
{
    const int tid  = threadIdx.x;
    const int lane = tid & 31, wid = tid >> 5;
    const int gid  = lane >> 2, tig = lane & 3;
    const int wm   = wid & 1, wn = wid >> 1;        // 2 x 2 warps, tile 64x64
    constexpr int K   = NK * KC;
    constexpr int TOT = NSEG * NK;

    float acc[4][8][4];
    #pragma unroll
    for (int i = 0; i < 4; i++)
        #pragma unroll
        for (int j = 0; j < 8; j++)
            #pragma unroll
            for (int q = 0; q < 4; q++) acc[i][j][q] = 0.0f;

    auto fill = [&](int lc) {
        const int c   = cc + lc;
        const int stg = c % 3;
        const int seg = lc / NK, kk = lc % NK;
        if (c >= 3) mbar_wait(EMPTYB(stg), (uint32_t)(((c / 3) - 1) & 1));
        const uint32_t base = sb + SM_STAGE0 + stg * STAGE_BYTES;
        const __half* Ap = Asrc + kk * KC;
        const __half* Bp = Wbase + (size_t)seg * ((size_t)NC * K) + kk * KC;
        #pragma unroll
        for (int i = 0; i < 8; i++) {                 // A: 128 rows x 8 x 16B
            int f = tid + i * NT, r = f >> 3, cq = f & 7;
            cpasync16(base + (uint32_t)(r * LD + cq * 8) * 2,
                      Ap + (size_t)r * As + cq * 8);
        }
        #pragma unroll
        for (int i = 0; i < 8; i++) {                 // B: 128 rows x 8 x 16B
            int f = tid + i * NT, r = f >> 3, cq = f & 7;
            cpasync16(base + A_BYTES + (uint32_t)(r * LD + cq * 8) * 2,
                      Bp + (size_t)r * K + cq * 8);
        }
        cp_mbar_arrive(FULLB(stg));
    };

    // per-lane ldmatrix byte offsets (b16, 16B granules)
    const uint32_t aoff = (uint32_t)(((lane & 15) * LD + (lane >> 4) * 8) * 2);
    const uint32_t boff = (uint32_t)(((((lane >> 4) & 1) * 8 + (lane & 7)) * LD
                                      + ((lane >> 3) & 1) * 8) * 2);

    auto compute = [&](int stg) {
        const uint32_t Ab = sb + SM_STAGE0 + stg * STAGE_BYTES
                          + (uint32_t)(wm * 64 * LD * 2) + aoff;
        const uint32_t Bb = sb + SM_STAGE0 + stg * STAGE_BYTES + A_BYTES
                          + (uint32_t)(wn * 64 * LD * 2) + boff;
        #pragma unroll
        for (int ks = 0; ks < 4; ks++) {              // 4 x k16 = KC 64
            const uint32_t k0b = (uint32_t)(ks * 32); // 16 halfs = 32B
            uint32_t a[4][4];
            #pragma unroll
            for (int mf = 0; mf < 4; mf++)
                ldsm4(a[mf], Ab + (uint32_t)(mf * 16 * LD * 2) + k0b);
            #pragma unroll
            for (int p = 0; p < 4; p++) {
                uint32_t bt[4];                       // n16 x k16 (two n8 frags)
                ldsm4(bt, Bb + (uint32_t)(p * 16 * LD * 2) + k0b);
                #pragma unroll
                for (int mf = 0; mf < 4; mf++) {
                    mma16(acc[mf][2 * p],     a[mf], bt);
                    mma16(acc[mf][2 * p + 1], a[mf], bt + 2);
                }
            }
        }
    };

    fill(0); fill(1);

    #pragma unroll 1
    for (int lc = 0; lc < TOT; lc++) {
        if (lc + 2 < TOT) fill(lc + 2);
        const int c = cc + lc, stg = c % 3;
        mbar_wait(FULLB(stg), (uint32_t)((c / 3) & 1));
        compute(stg);
        mbar_arrive(EMPTYB(stg));

        if ((lc & (NK - 1)) == NK - 1) {
            // segment epilogue (no barrier; overlaps other warps' compute)
            const int seg = lc / NK;
            #pragma unroll
            for (int mf = 0; mf < 4; mf++) {
                #pragma unroll
                for (int nf = 0; nf < 8; nf++) {
                    const int rr  = wm * 64 + mf * 16 + gid;
                    const int col = seg * NC + wn * 64 + nf * 8 + tig * 2;
                    const float b0 = __ldg(biasBase + col);
                    const float b1 = __ldg(biasBase + col + 1);
                    float v00 = acc[mf][nf][0] + b0, v01 = acc[mf][nf][1] + b1;
                    float v10 = acc[mf][nf][2] + b0, v11 = acc[mf][nf][3] + b1;
                    if (!ISOUT) {
                        v00 = fmaxf(v00, 0.0f); v01 = fmaxf(v01, 0.0f);
                        v10 = fmaxf(v10, 0.0f); v11 = fmaxf(v11, 0.0f);
                        __half* hd = (__half*)dstBase;
                        *reinterpret_cast<__half2*>(hd + (size_t)rr * dstride + col)
                            = __floats2half2_rn(v00, v01);
                        *reinterpret_cast<__half2*>(hd + (size_t)(rr + 8) * dstride + col)
                            = __floats2half2_rn(v10, v11);
                    } else {
                        float* fd = (float*)dstBase;
                        *reinterpret_cast<float2*>(fd + (size_t)rr * dstride + col)
                            = make_float2(v00, v01);
                        *reinterpret_cast<float2*>(fd + (size_t)(rr + 8) * dstride + col)
                            = make_float2(v10, v11);
                    }
                    acc[mf][nf][0] = 0.0f; acc[mf][nf][1] = 0.0f;
                    acc[mf][nf][2] = 0.0f; acc[mf][nf][3] = 0.0f;
                }
            }
        }
    }
    cc += TOT;

    if (!ISOUT) {   // h must be globally visible to next layer's cp.async
        asm volatile("membar.gl;" ::: "memory");
        __syncthreads();
    }
}

__global__ void __launch_bounds__(NT, 2)
multinet16(const float* __restrict__ b1, const float* __restrict__ b2,
           const float* __restrict__ b3, float* __restrict__ out)
{
    extern __shared__ float smf[];
    const uint32_t sb = smem_u32(smf);
    const int m0 = blockIdx.x * MT;
    const int g  = blockIdx.y;

    if (threadIdx.x == 0) {
        #pragma unroll
        for (int s = 0; s < 3; s++) {
            mbar_init(FULLB(s), NT);
            mbar_init(EMPTYB(s), NT);
        }
    }
    __syncthreads();

    __half* h1 = g_h1 + ((size_t)g * BATCH + m0) * D_H;
    __half* h2 = g_h2 + ((size_t)g * BATCH + m0) * D_H;

    int cc = 0;
    // layer 1: 4 segs x 4 chunks (K=256)
    run_layer<4, 4, false>(cc, sb, g_xh + (size_t)m0 * D_IN, D_IN,
                           g_w1h + (size_t)g * D_H * D_IN,
                           b1 + (size_t)g * D_H, h1, D_H);
    // layer 2: 4 segs x 8 chunks (K=512)
    run_layer<4, 8, false>(cc, sb, h1, D_H,
                           g_w2h + (size_t)g * D_H * D_H,
                           b2 + (size_t)g * D_H, h2, D_H);
    // layer 3: 1 seg x 8 chunks (identity, fp32 out)
    run_layer<1, 8, true>(cc, sb, h2, D_H,
                          g_w3h + (size_t)g * D_OUT * D_H,
                          b3 + (size_t)g * D_OUT,
                          out + (size_t)m0 * (NETS * D_OUT) + g * D_OUT,
                          NETS * D_OUT);
}

// Fused fp32 -> fp16(rn) conversion of x, W1, W2, W3 (one launch).
__global__ void round_all(const float* __restrict__ x,
                          const float* __restrict__ W1,
                          const float* __restrict__ W2,
                          const float* __restrict__ W3)
{
    constexpr size_t N0 = (size_t)BATCH * D_IN / 4;
    constexpr size_t N1 = (size_t)NETS * D_H * D_IN / 4;
    constexpr size_t N2 = (size_t)NETS * D_H * D_H / 4;
    constexpr size_t N3 = (size_t)NETS * D_OUT * D_H / 4;

    size_t j = (size_t)blockIdx.x * blockDim.x + threadIdx.x;
    const float4* src; __half2* dst;
    if (j < N0)              { src = (const float4*)x;  dst = (__half2*)g_xh; }
    else if ((j -= N0) < N1) { src = (const float4*)W1; dst = (__half2*)g_w1h; }
    else if ((j -= N1) < N2) { src = (const float4*)W2; dst = (__half2*)g_w2h; }
    else if ((j -= N2) < N3) { src = (const float4*)W3; dst = (__half2*)g_w3h; }
    else return;

    float4 v = src[j];
    dst[2 * j]     = __floats2half2_rn(v.x, v.y);
    dst[2 * j + 1] = __floats2half2_rn(v.z, v.w);
}

extern "C" void kernel_launch(void* const* d_in, const int* in_sizes, int n_in,
                              void* d_out, int out_size)
{
    const float* x  = (const float*)d_in[0];
    const float* W1 = (const float*)d_in[1];
    const float* b1 = (const float*)d_in[2];
    const float* W2 = (const float*)d_in[3];
    const float* b2 = (const float*)d_in[4];
    const float* W3 = (const float*)d_in[5];
    const float* b3 = (const float*)d_in[6];
    float* out = (float*)d_out;

    constexpr size_t TOTQ = ((size_t)BATCH * D_IN + (size_t)NETS * D_H * D_IN
                           + (size_t)NETS * D_H * D_H + (size_t)NETS * D_OUT * D_H) / 4;
    round_all<<<(unsigned)((TOTQ + 255) / 256), 256>>>(x, W1, W2, W3);

    cudaFuncSetAttribute(multinet16,
                         cudaFuncAttributeMaxDynamicSharedMemorySize, SMEM_BYTES);
    dim3 grid(BATCH / MT, NETS);   // 32 x 32 = 1024 CTAs
    multinet16<<<grid, NT, SMEM_BYTES>>>(b1, b2, b3, out);
}